// round 14
// baseline (speedup 1.0000x reference)
#include <cuda_runtime.h>
#include <cuda_fp16.h>
#include <cstdint>
#include <math.h>

#define N_NODES 8192
#define D_DIM   128
#define CAP     192           // nnz/row ~ 83 +/- 9  -> 12 sigma margin
#define WPC     8             // warps (rows) per CTA -> 256 threads

// device scratch (no cudaMalloc allowed)
__device__ float  g_s[N_NODES];                 // per-node scores
__device__ __half g_emb_h[N_NODES * D_DIM];     // fp16 copy of emb (2MB)

// ---------------------------------------------------------------------------
// Kernel 1: one pass over emb computes BOTH g_s = emb @ H_v and the fp16 copy.
// ---------------------------------------------------------------------------
__global__ __launch_bounds__(256)
void prep_kernel(const float* __restrict__ emb,
                 const float* __restrict__ hv) {
    const int w    = threadIdx.x >> 5;
    const int lane = threadIdx.x & 31;
    const int row  = blockIdx.x * WPC + w;

    const float4* e4 = reinterpret_cast<const float4*>(emb);
    const float4  h  = reinterpret_cast<const float4*>(hv)[lane];

    float4 a = e4[(size_t)row * 32 + lane];

    __half2 h0 = __floats2half2_rn(a.x, a.y);
    __half2 h1 = __floats2half2_rn(a.z, a.w);
    uint2 u;
    u.x = *reinterpret_cast<unsigned*>(&h0);
    u.y = *reinterpret_cast<unsigned*>(&h1);
    reinterpret_cast<uint2*>(g_emb_h)[(size_t)row * 32 + lane] = u;

    float d = a.x * h.x + a.y * h.y + a.z * h.z + a.w * h.w;
    #pragma unroll
    for (int off = 16; off > 0; off >>= 1)
        d += __shfl_xor_sync(0xFFFFFFFFu, d, off);
    if (lane == 0) g_s[row] = d;
}

// ---------------------------------------------------------------------------
// Kernel 2: fused scan + softmax + gather, HALF-ROW SOFTWARE PIPELINE.
// ONE WARP PER ROW, single wave (1024 CTAs <= 148 x 7).
//   batches 0..7  : pure scan (R6 ballot compaction)
//   batches 8..15 : issue scan loads, then gather a chunk of the STAGE-1
//                   list (stable, completed region) while they fly, then
//                   compact. Hides phase-C latency under phase-A DRAM waits.
//   tail          : gather the remaining entries.
// exp inside gather (lane-redundant, warp-uniform lsum; max-subtraction
// unnecessary since |logit| < ~6). Normalize once at the end.
// ---------------------------------------------------------------------------
__global__ __launch_bounds__(WPC * 32, 7)
void fused_kernel(const float* __restrict__ adj,
                  float* __restrict__ out) {
    const int w    = threadIdx.x >> 5;
    const int lane = threadIdx.x & 31;
    const int row  = blockIdx.x * WPC + w;
    const unsigned below = (1u << lane) - 1u;

    __shared__ unsigned short s_cols[WPC][CAP];
    __shared__ float          s_vals[WPC][CAP];

    const float4* rowp = reinterpret_cast<const float4*>(adj + (size_t)row * N_NODES);
    const uint2*  embh = reinterpret_cast<const uint2*>(g_emb_h);   // row = 32 uint2

    int    count = 0;
    int    done  = 0;
    int    K     = 0;          // size of stage-1 (stable) list region
    int    chunk = 0;
    float  lsum  = 0.0f;       // warp-uniform
    float4 acc   = make_float4(0.f, 0.f, 0.f, 0.f);

    #pragma unroll 1
    for (int t = 0; t < 16; t++) {
        // ---- issue this batch's 4 streaming loads ----
        float4 v[4];
        #pragma unroll
        for (int j = 0; j < 4; j++)
            v[j] = __ldcs(&rowp[(t * 4 + j) * 32 + lane]);

        // ---- stage 2: gather a chunk of the stable list while loads fly ----
        if (t >= 8) {
            int target = done + chunk;
            if (target > K) target = K;
            int k = done;
            for (; k + 2 <= target; k += 2) {
                int   c0v = s_cols[w][k];
                int   c1v = s_cols[w][k + 1];
                float a0  = s_vals[w][k];
                float a1  = s_vals[w][k + 1];
                float w0  = __expf(a0 * __ldg(&g_s[c0v]));
                float w1  = __expf(a1 * __ldg(&g_s[c1v]));
                uint2 e0  = __ldg(&embh[(size_t)c0v * 32 + lane]);
                uint2 e1  = __ldg(&embh[(size_t)c1v * 32 + lane]);
                lsum += w0 + w1;
                float2 f;
                f = __half22float2(*reinterpret_cast<__half2*>(&e0.x)); acc.x += w0 * f.x; acc.y += w0 * f.y;
                f = __half22float2(*reinterpret_cast<__half2*>(&e0.y)); acc.z += w0 * f.x; acc.w += w0 * f.y;
                f = __half22float2(*reinterpret_cast<__half2*>(&e1.x)); acc.x += w1 * f.x; acc.y += w1 * f.y;
                f = __half22float2(*reinterpret_cast<__half2*>(&e1.y)); acc.z += w1 * f.x; acc.w += w1 * f.y;
            }
            for (; k < target; k++) {
                int   cv = s_cols[w][k];
                float av = s_vals[w][k];
                float wv = __expf(av * __ldg(&g_s[cv]));
                uint2 e  = __ldg(&embh[(size_t)cv * 32 + lane]);
                lsum += wv;
                float2 f;
                f = __half22float2(*reinterpret_cast<__half2*>(&e.x)); acc.x += wv * f.x; acc.y += wv * f.y;
                f = __half22float2(*reinterpret_cast<__half2*>(&e.y)); acc.z += wv * f.x; acc.w += wv * f.y;
            }
            done = target;
        }

        // ---- ballot-compact this batch (R6 scheme) ----
        #pragma unroll
        for (int j = 0; j < 4; j++) {
            float vv[4] = {v[j].x, v[j].y, v[j].z, v[j].w};
            bool any = (vv[0] != 0.f) | (vv[1] != 0.f) | (vv[2] != 0.f) | (vv[3] != 0.f);
            if (__ballot_sync(0xFFFFFFFFu, any)) {
                const int c0 = ((t * 4 + j) * 32 + lane) * 4;
                #pragma unroll
                for (int l = 0; l < 4; l++) {
                    bool nz = (vv[l] != 0.0f);
                    unsigned m = __ballot_sync(0xFFFFFFFFu, nz);
                    if (m) {
                        if (nz) {
                            int idx = count + __popc(m & below);
                            if (idx < CAP) {
                                s_cols[w][idx] = (unsigned short)(c0 + l);
                                s_vals[w][idx] = vv[l];
                            }
                        }
                        count += __popc(m);
                    }
                }
            }
        }

        // ---- end of stage 1: freeze the stable region ----
        if (t == 7) {
            __syncwarp();
            K = min(count, CAP);
            chunk = (K + 7) >> 3;
        }
    }
    __syncwarp();

    // ---- tail gather: entries [done, n) with 4 loads in flight ----
    const int n = min(count, CAP);
    int k = done;
    for (; k + 4 <= n; k += 4) {
        uint2 e[4]; float wv[4];
        #pragma unroll
        for (int i = 0; i < 4; i++) {
            int   cv = s_cols[w][k + i];
            float av = s_vals[w][k + i];
            wv[i] = __expf(av * __ldg(&g_s[cv]));
            e[i]  = __ldg(&embh[(size_t)cv * 32 + lane]);
        }
        #pragma unroll
        for (int i = 0; i < 4; i++) {
            lsum += wv[i];
            float2 f0 = __half22float2(*reinterpret_cast<__half2*>(&e[i].x));
            float2 f1 = __half22float2(*reinterpret_cast<__half2*>(&e[i].y));
            acc.x += wv[i] * f0.x;
            acc.y += wv[i] * f0.y;
            acc.z += wv[i] * f1.x;
            acc.w += wv[i] * f1.y;
        }
    }
    for (; k < n; k++) {
        int   cv = s_cols[w][k];
        float av = s_vals[w][k];
        float wv = __expf(av * __ldg(&g_s[cv]));
        uint2 e  = __ldg(&embh[(size_t)cv * 32 + lane]);
        lsum += wv;
        float2 f0 = __half22float2(*reinterpret_cast<__half2*>(&e.x));
        float2 f1 = __half22float2(*reinterpret_cast<__half2*>(&e.y));
        acc.x += wv * f0.x;
        acc.y += wv * f0.y;
        acc.z += wv * f1.x;
        acc.w += wv * f1.y;
    }

    const float inv = 1.0f / lsum;
    acc.x *= inv; acc.y *= inv; acc.z *= inv; acc.w *= inv;
    float4* outp = reinterpret_cast<float4*>(out) + (size_t)row * 32 + lane;
    __stcs(outp, acc);
}

// ---------------------------------------------------------------------------
extern "C" void kernel_launch(void* const* d_in, const int* in_sizes, int n_in,
                              void* d_out, int out_size) {
    const float* emb = nullptr;
    const float* adj = nullptr;
    const float* hv  = nullptr;
    for (int i = 0; i < n_in; i++) {
        long sz = in_sizes[i];
        if (sz == (long)N_NODES * D_DIM)      emb = (const float*)d_in[i];
        else if (sz == D_DIM)                 hv  = (const float*)d_in[i];
        else                                  adj = (const float*)d_in[i];
    }
    float* out = (float*)d_out;

    prep_kernel<<<N_NODES / WPC, WPC * 32>>>(emb, hv);
    fused_kernel<<<N_NODES / WPC, WPC * 32>>>(adj, out);
}

// round 15
// speedup vs baseline: 1.3573x; 1.3573x over previous
#include <cuda_runtime.h>
#include <cuda_fp16.h>
#include <cstdint>
#include <math.h>

#define N_NODES 8192
#define D_DIM   128
#define CAP     192           // nnz/row ~ 83 +/- 9  -> 12 sigma margin
#define WPC     8             // warps (rows) per CTA -> 256 threads

// device scratch (no cudaMalloc allowed)
__device__ float  g_s[N_NODES];                 // per-node scores
__device__ __half g_emb_h[N_NODES * D_DIM];     // fp16 copy of emb (2MB)

// ---------------------------------------------------------------------------
// Kernel 1: one pass over emb computes BOTH g_s = emb @ H_v and the fp16 copy.
// ---------------------------------------------------------------------------
__global__ __launch_bounds__(256)
void prep_kernel(const float* __restrict__ emb,
                 const float* __restrict__ hv) {
    const int w    = threadIdx.x >> 5;
    const int lane = threadIdx.x & 31;
    const int row  = blockIdx.x * WPC + w;

    const float4* e4 = reinterpret_cast<const float4*>(emb);
    const float4  h  = reinterpret_cast<const float4*>(hv)[lane];

    float4 a = e4[(size_t)row * 32 + lane];

    __half2 h0 = __floats2half2_rn(a.x, a.y);
    __half2 h1 = __floats2half2_rn(a.z, a.w);
    uint2 u;
    u.x = *reinterpret_cast<unsigned*>(&h0);
    u.y = *reinterpret_cast<unsigned*>(&h1);
    reinterpret_cast<uint2*>(g_emb_h)[(size_t)row * 32 + lane] = u;

    float d = a.x * h.x + a.y * h.y + a.z * h.z + a.w * h.w;
    #pragma unroll
    for (int off = 16; off > 0; off >>= 1)
        d += __shfl_xor_sync(0xFFFFFFFFu, d, off);
    if (lane == 0) g_s[row] = d;
}

// ---------------------------------------------------------------------------
// Kernel 2: fused scan + softmax + gather (R6 structure — measured optimum).
// ONE WARP PER ROW, single wave (1024 CTAs <= 148 SMs x 7 CTAs/SM).
//  A: stream adj row (__ldcs, 4 float4 in flight), ballot-compact nonzeros
//     into per-warp smem list (u16 col, f32 adj); fully-zero 512B groups
//     skipped with one ballot.
//  B: w = exp(adj*s) + warp-reduce sum (max-subtraction unnecessary: |logit|<6)
//  C: fp16 gather, lane owns 4 output dims, 4 loads in flight; streamed store.
// ---------------------------------------------------------------------------
__global__ __launch_bounds__(WPC * 32, 7)
void fused_kernel(const float* __restrict__ adj,
                  float* __restrict__ out) {
    const int w    = threadIdx.x >> 5;
    const int lane = threadIdx.x & 31;
    const int row  = blockIdx.x * WPC + w;
    const unsigned below = (1u << lane) - 1u;

    __shared__ unsigned short s_cols[WPC][CAP];
    __shared__ float          s_vals[WPC][CAP];

    const float4* rowp = reinterpret_cast<const float4*>(adj + (size_t)row * N_NODES);

    // ---- phase A: stream + ballot compaction ----
    int count = 0;
    for (int g = 0; g < 64; g += 4) {
        float4 v[4];
        #pragma unroll
        for (int j = 0; j < 4; j++)
            v[j] = __ldcs(&rowp[(g + j) * 32 + lane]);
        #pragma unroll
        for (int j = 0; j < 4; j++) {
            float vv[4] = {v[j].x, v[j].y, v[j].z, v[j].w};
            bool any = (vv[0] != 0.f) | (vv[1] != 0.f) | (vv[2] != 0.f) | (vv[3] != 0.f);
            if (__ballot_sync(0xFFFFFFFFu, any)) {
                const int c0 = ((g + j) * 32 + lane) * 4;
                #pragma unroll
                for (int l = 0; l < 4; l++) {
                    bool nz = (vv[l] != 0.0f);
                    unsigned m = __ballot_sync(0xFFFFFFFFu, nz);
                    if (m) {
                        if (nz) {
                            int idx = count + __popc(m & below);
                            if (idx < CAP) {
                                s_cols[w][idx] = (unsigned short)(c0 + l);
                                s_vals[w][idx] = vv[l];
                            }
                        }
                        count += __popc(m);
                    }
                }
            }
        }
    }
    __syncwarp();

    // ---- phase B: exp + sum over the compacted list ----
    int n = min(count, CAP);
    float lsum = 0.0f;
    for (int k = lane; k < n; k += 32) {
        int col  = s_cols[w][k];
        float wv = __expf(s_vals[w][k] * g_s[col]);
        s_vals[w][k] = wv;
        lsum += wv;
    }
    #pragma unroll
    for (int off = 16; off > 0; off >>= 1)
        lsum += __shfl_xor_sync(0xFFFFFFFFu, lsum, off);
    const float inv = 1.0f / lsum;
    __syncwarp();

    // ---- phase C: fp16 gather. lane owns dims [lane*4, lane*4+4) ----
    const uint2* embh = reinterpret_cast<const uint2*>(g_emb_h);  // row = 32 uint2
    float4 acc = make_float4(0.f, 0.f, 0.f, 0.f);
    int k = 0;
    for (; k + 4 <= n; k += 4) {
        uint2 e[4]; float wv[4];
        #pragma unroll
        for (int i = 0; i < 4; i++) {
            int col = s_cols[w][k + i];
            wv[i]   = s_vals[w][k + i];
            e[i]    = __ldg(&embh[(size_t)col * 32 + lane]);
        }
        #pragma unroll
        for (int i = 0; i < 4; i++) {
            float2 f0 = __half22float2(*reinterpret_cast<__half2*>(&e[i].x));
            float2 f1 = __half22float2(*reinterpret_cast<__half2*>(&e[i].y));
            acc.x += wv[i] * f0.x;
            acc.y += wv[i] * f0.y;
            acc.z += wv[i] * f1.x;
            acc.w += wv[i] * f1.y;
        }
    }
    for (; k < n; k++) {
        int col  = s_cols[w][k];
        float wv = s_vals[w][k];
        uint2 e  = __ldg(&embh[(size_t)col * 32 + lane]);
        float2 f0 = __half22float2(*reinterpret_cast<__half2*>(&e.x));
        float2 f1 = __half22float2(*reinterpret_cast<__half2*>(&e.y));
        acc.x += wv * f0.x;
        acc.y += wv * f0.y;
        acc.z += wv * f1.x;
        acc.w += wv * f1.y;
    }
    acc.x *= inv; acc.y *= inv; acc.z *= inv; acc.w *= inv;
    float4* outp = reinterpret_cast<float4*>(out) + (size_t)row * 32 + lane;
    __stcs(outp, acc);
}

// ---------------------------------------------------------------------------
extern "C" void kernel_launch(void* const* d_in, const int* in_sizes, int n_in,
                              void* d_out, int out_size) {
    const float* emb = nullptr;
    const float* adj = nullptr;
    const float* hv  = nullptr;
    for (int i = 0; i < n_in; i++) {
        long sz = in_sizes[i];
        if (sz == (long)N_NODES * D_DIM)      emb = (const float*)d_in[i];
        else if (sz == D_DIM)                 hv  = (const float*)d_in[i];
        else                                  adj = (const float*)d_in[i];
    }
    float* out = (float*)d_out;

    prep_kernel<<<N_NODES / WPC, WPC * 32>>>(emb, hv);
    fused_kernel<<<N_NODES / WPC, WPC * 32>>>(adj, out);
}